// round 17
// baseline (speedup 1.0000x reference)
#include <cuda_runtime.h>
#include <cooperative_groups.h>
namespace cg = cooperative_groups;

#define BB 64
#define TT 2048
#define DD 512

// Scratch (allocation-free contract: __device__ globals)
__device__ float g_phis[BB * DD];
__device__ float g_v[BB * DD];
__device__ float g_e[BB * TT];
__device__ float g_hsum[BB * TT];

// ---------------------------------------------------------------------------
// k_prep: COOPERATIVE fusion of phi + v (one launch instead of two).
// 64 blocks x 512 threads, all resident -> grid.sync() legal.
//
// Phase 1 (phi_s[b,a] = s[b]·phi_w[a] + phi_b[a]):
//   1024 warps; warp handles 2 a's (pinned in regs) x 16 b's.
//   a-pair: (blockIdx%32)*16 + (warp%8)*2 ; b-range: (blockIdx/32)*32+(warp/8)*16.
//   s/phi_w rows are L1-shared across the block's warps.
// Phase 2 (v[b,k] = sum_a phi_s[b,a] * psi_w[a,k]):
//   exact round-16 k_v body; block = (b-quad = blockIdx%16, k-slice = blockIdx/16).
// psi_b dropped: softmax is shift-invariant to the per-b constant it adds.
// ---------------------------------------------------------------------------
__global__ void __launch_bounds__(512, 1) k_prep(const float* __restrict__ s,
                                                 const float* __restrict__ phi_w,
                                                 const float* __restrict__ phi_b,
                                                 const float* __restrict__ psi_w) {
    const int tid  = threadIdx.x;          // 512
    const int lane = tid & 31;
    const int warp = tid >> 5;             // 16 warps

    // ---------------- Phase 1: phi ----------------
    {
        const int a0 = (blockIdx.x & 31) * 16 + (warp & 7) * 2;
        const int a1 = a0 + 1;
        const float4* w0 = (const float4*)(phi_w + (size_t)a0 * DD);
        const float4* w1 = (const float4*)(phi_w + (size_t)a1 * DD);
        float4 wa[4], wb[4];
        #pragma unroll
        for (int j = 0; j < 4; j++) { wa[j] = w0[lane + 32 * j]; wb[j] = w1[lane + 32 * j]; }
        const float bias0 = phi_b[a0];
        const float bias1 = phi_b[a1];

        const int bbase = (blockIdx.x >> 5) * 32 + (warp >> 3) * 16;
        #pragma unroll 1
        for (int bi = 0; bi < 16; bi++) {
            const int b = bbase + bi;
            const float4* s4 = (const float4*)(s + (size_t)b * DD);
            float acc0 = 0.f, acc1 = 0.f;
            #pragma unroll
            for (int j = 0; j < 4; j++) {
                const float4 sv = s4[lane + 32 * j];
                acc0 += wa[j].x * sv.x + wa[j].y * sv.y + wa[j].z * sv.z + wa[j].w * sv.w;
                acc1 += wb[j].x * sv.x + wb[j].y * sv.y + wb[j].z * sv.z + wb[j].w * sv.w;
            }
            // Folded 2-value warp reduction: 6 SHFLs, depth 5.
            acc0 += __shfl_xor_sync(0xffffffffu, acc0, 16);
            acc1 += __shfl_xor_sync(0xffffffffu, acc1, 16);
            float x = (lane & 16) ? acc1 : acc0;
            #pragma unroll
            for (int off = 8; off; off >>= 1)
                x += __shfl_xor_sync(0xffffffffu, x, off);
            if ((lane & 15) == 0) {
                const int a = (lane == 0) ? a0 : a1;
                g_phis[b * DD + a] = x + ((lane == 0) ? bias0 : bias1);
            }
        }
    }

    cg::this_grid().sync();                // all phi_s visible

    // ---------------- Phase 2: v (exact k_v body) ----------------
    const int b0 = (blockIdx.x & 15) * 4;
    const int ks = blockIdx.x >> 4;        // k-slice: 32 float4 columns

    __shared__ float  ph[4][DD];
    __shared__ float4 part[4][16][32];

    #pragma unroll
    for (int j = 0; j < 4; j++)
        ph[j][tid] = g_phis[(size_t)(b0 + j) * DD + tid];
    __syncthreads();

    const float4* w4 = (const float4*)psi_w;     // [512][128] float4
    const int col = ks * 32 + lane;              // 0..127

    float4 acc[4];
    #pragma unroll
    for (int j = 0; j < 4; j++) acc[j] = make_float4(0.f, 0.f, 0.f, 0.f);

    const int abase = warp * 32;
    #pragma unroll 4
    for (int i = 0; i < 32; i++) {
        const int a = abase + i;
        const float4 w = w4[(size_t)a * 128 + col];
        #pragma unroll
        for (int j = 0; j < 4; j++) {
            const float p = ph[j][a];
            acc[j].x += p * w.x; acc[j].y += p * w.y;
            acc[j].z += p * w.z; acc[j].w += p * w.w;
        }
    }
    #pragma unroll
    for (int j = 0; j < 4; j++) part[j][warp][lane] = acc[j];
    __syncthreads();

    if (warp < 4) {
        float4 r = part[warp][0][lane];
        #pragma unroll
        for (int w = 1; w < 16; w++) {
            float4 p = part[warp][w][lane];
            r.x += p.x; r.y += p.y; r.z += p.z; r.w += p.w;
        }
        ((float4*)g_v)[(size_t)(b0 + warp) * 128 + col] = r;
    }
}

// ---------------------------------------------------------------------------
// k_scores: the DRAM-bound pass (one 268 MB streaming read of h).
// EXACT round-16 proven core (53.7us total): grid 8192 x 256,
// launch_bounds(256,4), v staged via smem once per block, __ldcs h loads.
// ---------------------------------------------------------------------------
__global__ void __launch_bounds__(256, 4) k_scores(const float* __restrict__ h) {
    const int tid  = threadIdx.x;
    const int lane = tid & 31;
    const int warp = tid >> 5;
    const int row0 = blockIdx.x * 16 + warp * 2;
    const int b    = blockIdx.x >> 7;      // 128 blocks per b

    __shared__ float sh_v[DD];
    ((float2*)sh_v)[tid] = ((const float2*)(g_v + (size_t)b * DD))[tid];
    __syncthreads();

    const float4* sv4 = (const float4*)sh_v;
    float4 v[4];
    #pragma unroll
    for (int j = 0; j < 4; j++) v[j] = sv4[lane + 32 * j];

    const float4* ha = (const float4*)(h + (size_t)row0 * DD);
    const float4* hb = ha + 128;
    float4 A[4], B[4];
    #pragma unroll
    for (int j = 0; j < 4; j++) A[j] = __ldcs(&ha[lane + 32 * j]);
    #pragma unroll
    for (int j = 0; j < 4; j++) B[j] = __ldcs(&hb[lane + 32 * j]);

    float e0 = 0.f, s0 = 0.f, e1 = 0.f, s1 = 0.f;
    #pragma unroll
    for (int j = 0; j < 4; j++) {
        e0 += A[j].x * v[j].x + A[j].y * v[j].y + A[j].z * v[j].z + A[j].w * v[j].w;
        s0 += (A[j].x + A[j].y) + (A[j].z + A[j].w);
        e1 += B[j].x * v[j].x + B[j].y * v[j].y + B[j].z * v[j].z + B[j].w * v[j].w;
        s1 += (B[j].x + B[j].y) + (B[j].z + B[j].w);
    }
    #pragma unroll
    for (int off = 16; off; off >>= 1) {
        e0 += __shfl_xor_sync(0xffffffffu, e0, off);
        s0 += __shfl_xor_sync(0xffffffffu, s0, off);
        e1 += __shfl_xor_sync(0xffffffffu, e1, off);
        s1 += __shfl_xor_sync(0xffffffffu, s1, off);
    }
    if (lane == 0) {
        *(float2*)(g_e    + row0) = make_float2(e0, e1);
        *(float2*)(g_hsum + row0) = make_float2(s0, s1);
    }
}

// ---------------------------------------------------------------------------
// k_softmax: per-b softmax over T=2048 + output c = alpha * hsum.
// EXACT round-16 version: 64 blocks x 1024 threads (2 e/thread).
// ---------------------------------------------------------------------------
__global__ void k_softmax(float* __restrict__ out) {
    const int b    = blockIdx.x;
    const int tid  = threadIdx.x;          // 1024 -> 2 elems/thread
    const int lane = tid & 31;
    const int warp = tid >> 5;             // 32 warps
    __shared__ float red[32];

    const float2 e  = ((const float2*)(g_e    + (size_t)b * TT))[tid];
    const float2 hs = ((const float2*)(g_hsum + (size_t)b * TT))[tid];

    float m = fmaxf(e.x, e.y);
    #pragma unroll
    for (int off = 16; off; off >>= 1)
        m = fmaxf(m, __shfl_xor_sync(0xffffffffu, m, off));
    if (lane == 0) red[warp] = m;
    __syncthreads();
    float M = red[0];
    #pragma unroll
    for (int w = 1; w < 32; w++) M = fmaxf(M, red[w]);
    __syncthreads();

    const float ex0 = __expf(e.x - M);
    const float ex1 = __expf(e.y - M);
    float sum = ex0 + ex1;
    #pragma unroll
    for (int off = 16; off; off >>= 1)
        sum += __shfl_xor_sync(0xffffffffu, sum, off);
    if (lane == 0) red[warp] = sum;
    __syncthreads();
    float S = 0.f;
    #pragma unroll
    for (int w = 0; w < 32; w++) S += red[w];
    const float inv = 1.f / S;

    float2 o;
    o.x = ex0 * inv * hs.x;
    o.y = ex1 * inv * hs.y;
    ((float2*)(out + (size_t)b * TT))[tid] = o;
}

// ---------------------------------------------------------------------------
extern "C" void kernel_launch(void* const* d_in, const int* in_sizes, int n_in,
                              void* d_out, int out_size) {
    const float* s     = (const float*)d_in[0];   // [64, 512]
    const float* h     = (const float*)d_in[1];   // [64, 2048, 512]
    const float* phi_w = (const float*)d_in[2];   // [512, 512]
    const float* phi_b = (const float*)d_in[3];   // [512]
    const float* psi_w = (const float*)d_in[4];   // [512, 512]
    // d_in[5] = psi_b: unused (softmax shift invariance)
    float* out = (float*)d_out;                   // [64, 2048] fp32

    // Cooperative launch (CUDA 12+ attribute; graph-capturable).
    cudaLaunchConfig_t cfg = {};
    cfg.gridDim  = dim3(64);
    cfg.blockDim = dim3(512);
    cudaLaunchAttribute attr[1];
    attr[0].id = cudaLaunchAttributeCooperative;
    attr[0].val.cooperative = 1;
    cfg.attrs    = attr;
    cfg.numAttrs = 1;
    cudaLaunchKernelEx(&cfg, k_prep, s, phi_w, phi_b, psi_w);

    k_scores<<<8192, 256>>>(h);    // 8192 * 16 rows = 131072 = BB*TT
    k_softmax<<<64, 1024>>>(out);
}